// round 15
// baseline (speedup 1.0000x reference)
#include <cuda_runtime.h>
#include <cuda_fp16.h>
#include <math.h>
#include <stdint.h>

#define S_LEN 3136
#define E_DIM 1024
#define H_NUM 16
#define D_DIM 64

// ---------------------------------------------------------------------------
// Device scratch (allocation is forbidden)
// ---------------------------------------------------------------------------
__device__ float g_qkv[3][H_NUM * S_LEN * D_DIM];   // fp32 head-major q,k,v

__device__ __align__(16) __half g_Hh[S_LEN * E_DIM];            // hidden fp16
__device__ __align__(16) __half g_Wh[4][E_DIM * E_DIM];         // weights fp16
__device__ __align__(16) __half g_Qh[H_NUM * S_LEN * D_DIM];    // q fp16 (scaled 1/8)
__device__ __align__(16) __half g_Kh[H_NUM * S_LEN * D_DIM];    // k fp16
__device__ __align__(16) __half g_Vt[H_NUM * D_DIM * S_LEN];    // [h][d][s] fp16
__device__ __align__(16) __half g_E[(long)H_NUM * S_LEN * S_LEN]; // unnormalized exp
__device__ __align__(16) __half g_AO[S_LEN * E_DIM];            // normalized attn out

// ---------------------------------------------------------------------------
// PTX helpers
// ---------------------------------------------------------------------------
__device__ __forceinline__ uint32_t smem_u32(const void* p) {
    uint32_t a;
    asm("{ .reg .u64 t; cvta.to.shared.u64 t, %1; cvt.u32.u64 %0, t; }" : "=r"(a) : "l"(p));
    return a;
}
__device__ __forceinline__ void cp16(uint32_t dst, const void* src, int srcsize) {
    asm volatile("cp.async.cg.shared.global [%0], [%1], 16, %2;"
                 :: "r"(dst), "l"(src), "r"(srcsize));
}
__device__ __forceinline__ void cpcommit() { asm volatile("cp.async.commit_group;"); }
template <int N> __device__ __forceinline__ void cpwait() {
    asm volatile("cp.async.wait_group %0;" :: "n"(N));
}
__device__ __forceinline__ void ldm4(uint32_t* r, uint32_t a) {
    asm volatile("ldmatrix.sync.aligned.m8n8.x4.shared.b16 {%0,%1,%2,%3}, [%4];"
                 : "=r"(r[0]), "=r"(r[1]), "=r"(r[2]), "=r"(r[3]) : "r"(a));
}
__device__ __forceinline__ void mma16816(float* d, const uint32_t* a, const uint32_t* b) {
    asm volatile("mma.sync.aligned.m16n8k16.row.col.f32.f16.f16.f32 "
                 "{%0,%1,%2,%3}, {%4,%5,%6,%7}, {%8,%9}, {%0,%1,%2,%3};"
                 : "+f"(d[0]), "+f"(d[1]), "+f"(d[2]), "+f"(d[3])
                 : "r"(a[0]), "r"(a[1]), "r"(a[2]), "r"(a[3]), "r"(b[0]), "r"(b[1]));
}

// ---------------------------------------------------------------------------
// fp16 single/single TN GEMM for QKV-proj and out-proj (ldm4-paired B).
// EPI 0: fp32 C[z*cBatch + m*ldc + n]
// EPI 1: fp32 head-major qkv: C[(z*H + (n>>6))*S*64 + m*64 + (n&63)]
// ---------------------------------------------------------------------------
template <int EPI>
__global__ void __launch_bounds__(256, 1) mma_gemm(
    const __half* __restrict__ A, long aRow,
    const __half* __restrict__ B, long bRow, long bBatch,
    float* __restrict__ C, long ldc, long cBatch,
    int kChunks, int M_valid) {

    constexpr int AST = 80;
    constexpr int A_BYTES = 128 * AST;
    constexpr int B_BYTES = 128 * AST;
    constexpr int STAGE = A_BYTES + B_BYTES;

    extern __shared__ char smem[];
    const uint32_t sb = smem_u32(smem);

    const int tid = threadIdx.x;
    const int wid = tid >> 5, lane = tid & 31;
    const int warpM = (wid / 4) * 64;
    const int warpN = (wid % 4) * 32;

    const int mBase = blockIdx.y * 128;
    const int nBase = blockIdx.x * 128;
    const int z = blockIdx.z;
    B += bBatch * z;

    const int xrow = (lane & 7) + ((lane >> 4) << 3);
    const int xcol = ((lane >> 3) & 1) * 16;

    float acc[4][4][4];
#pragma unroll
    for (int i = 0; i < 4; i++)
#pragma unroll
        for (int j = 0; j < 4; j++)
#pragma unroll
            for (int q = 0; q < 4; q++) acc[i][j][q] = 0.0f;

    auto issue_loads = [&](int c) {
        const long k0 = (long)c * 32;
        const uint32_t st = sb + (c & 1) * STAGE;
        for (int i = tid; i < 512; i += 256) {
            const int r = i >> 2, u = i & 3;
            const int row = mBase + r;
            const int ok = (row < M_valid) ? 16 : 0;
            const long srow = (row < M_valid) ? row : (M_valid - 1);
            cp16(st + r * AST + u * 16, A + srow * aRow + k0 + u * 8, ok);
        }
        for (int i = tid; i < 512; i += 256) {
            const int r = i >> 2, u = i & 3;
            cp16(st + A_BYTES + r * AST + u * 16, B + (long)(nBase + r) * bRow + k0 + u * 8, 16);
        }
        cpcommit();
    };

    issue_loads(0);

    for (int c = 0; c < kChunks; c++) {
        if (c + 1 < kChunks) { issue_loads(c + 1); cpwait<1>(); }
        else                 { cpwait<0>(); }
        __syncthreads();

        const uint32_t st = sb + (c & 1) * STAGE;
        const uint32_t aB = st, bB = st + A_BYTES;

#pragma unroll
        for (int s = 0; s < 2; s++) {
            uint32_t af[4][4], bf[2][4];
            const int arow = warpM + (lane & 15);
            const uint32_t acol = s * 32 + (lane >> 4) * 16;
#pragma unroll
            for (int mi = 0; mi < 4; mi++)
                ldm4(af[mi], aB + (uint32_t)((arow + mi * 16) * AST) + acol);
#pragma unroll
            for (int n2 = 0; n2 < 2; n2++)
                ldm4(bf[n2], bB + (uint32_t)((warpN + n2 * 16 + xrow) * AST) + s * 32 + xcol);
#pragma unroll
            for (int mi = 0; mi < 4; mi++)
#pragma unroll
                for (int n2 = 0; n2 < 2; n2++) {
                    mma16816(acc[mi][n2 * 2 + 0], af[mi], &bf[n2][0]);
                    mma16816(acc[mi][n2 * 2 + 1], af[mi], &bf[n2][2]);
                }
        }
        __syncthreads();
    }

#pragma unroll
    for (int mi = 0; mi < 4; mi++) {
#pragma unroll
        for (int ni = 0; ni < 4; ni++) {
            const int rl0 = warpM + mi * 16 + (lane >> 2);
            const int col0 = nBase + warpN + ni * 8 + (lane & 3) * 2;
#pragma unroll
            for (int h = 0; h < 2; h++) {
                const int row = mBase + rl0 + h * 8;
                if (row >= M_valid) continue;
                const float v0 = acc[mi][ni][h * 2 + 0];
                const float v1 = acc[mi][ni][h * 2 + 1];
                if (EPI == 0) {
                    C[(long)z * cBatch + (long)row * ldc + col0] = v0;
                    C[(long)z * cBatch + (long)row * ldc + col0 + 1] = v1;
                } else {
                    const long o0 = ((long)z * H_NUM + (col0 >> 6)) * S_LEN * 64 + (long)row * 64 + (col0 & 63);
                    C[o0] = v0;
                    C[o0 + 1] = v1;
                }
            }
        }
    }
}

// ---------------------------------------------------------------------------
// Fused attention with in-kernel normalize epilogue.
//   Mainloop: S = Q Kt -> exp -> fp16 E write + reg rowsum -> AO += P*V.
//   Epilogue: AO *= 1/rowsum; warp re-reads its 16 own E rows (all 32 lanes
//   per row, inv broadcast via shfl), writes fp32 attn_weights.
// ---------------------------------------------------------------------------
__global__ void __launch_bounds__(256, 1) fused_attn(
    const __half* __restrict__ Qh, const __half* __restrict__ Kh,
    const __half* __restrict__ V,
    __half* __restrict__ E, __half* __restrict__ AO, float* __restrict__ W) {

    constexpr int QK_ST = 176;
    constexpr int V_ST  = 272;
    constexpr int Q_BYTES = 128 * QK_ST;
    constexpr int K_BYTES = 128 * QK_ST;
    constexpr int V_BYTES = 64 * V_ST;
    constexpr int STAGE = K_BYTES + V_BYTES;
    constexpr int NT = 25;

    extern __shared__ char smem[];
    const uint32_t sb = smem_u32(smem);
    const uint32_t qb = sb;
    const uint32_t stb = sb + Q_BYTES;

    const int tid = threadIdx.x;
    const int w = tid >> 5, lane = tid & 31;
    const int h = blockIdx.y;
    const int mBase = blockIdx.x * 128;
    const long hS = (long)h * S_LEN;

    for (int i = tid; i < 1024; i += 256) {
        const int r = i >> 3, u = i & 7;
        const int row = mBase + r;
        const int ok = (row < S_LEN) ? 16 : 0;
        const long srow = (row < S_LEN) ? row : (S_LEN - 1);
        cp16(qb + r * QK_ST + u * 16, Qh + (hS + srow) * 64 + u * 8, ok);
    }
    auto issue_kv = [&](int t) {
        const int kBase = t * 128;
        const uint32_t st = stb + (t & 1) * STAGE;
        for (int i = tid; i < 1024; i += 256) {
            const int r = i >> 3, u = i & 7;
            const int row = kBase + r;
            const int ok = (row < S_LEN) ? 16 : 0;
            const long srow = (row < S_LEN) ? row : (S_LEN - 1);
            cp16(st + r * QK_ST + u * 16, Kh + (hS + srow) * 64 + u * 8, ok);
        }
        for (int i = tid; i < 1024; i += 256) {
            const int r = i >> 4, u = i & 15;
            const int col = kBase + u * 8;
            const int ok = (col < S_LEN) ? 16 : 0;
            const long scol = (col < S_LEN) ? col : (S_LEN - 8);
            const long off = ((long)h * 64 + r) * S_LEN + scol;
            cp16(st + K_BYTES + r * V_ST + u * 16, V + off, ok);
        }
        cpcommit();
    };
    issue_kv(0);
    issue_kv(1);
    cpwait<1>();
    __syncthreads();

    uint32_t qf[4][4];
    {
        const int arow = w * 16 + (lane & 15);
        const uint32_t acol = (uint32_t)((lane >> 4) * 16);
#pragma unroll
        for (int ks = 0; ks < 4; ks++)
            ldm4(qf[ks], qb + (uint32_t)(arow * QK_ST) + ks * 32 + acol);
    }

    float acc_o[8][4];
#pragma unroll
    for (int i = 0; i < 8; i++)
#pragma unroll
        for (int q = 0; q < 4; q++) acc_o[i][q] = 0.0f;
    float rsum0 = 0.0f, rsum1 = 0.0f;

    const int row0 = mBase + w * 16 + (lane >> 2);
    const int row1 = row0 + 8;
    const int xrow = (lane & 7) + ((lane >> 4) << 3);
    const int xcol = ((lane >> 3) & 1) * 16;

    for (int t = 0; t < NT; t++) {
        const uint32_t st = stb + (t & 1) * STAGE;
        const int kBase = t * 128;

        float acc[16][4];
#pragma unroll
        for (int i = 0; i < 16; i++)
#pragma unroll
            for (int q = 0; q < 4; q++) acc[i][q] = 0.0f;
#pragma unroll
        for (int ks = 0; ks < 4; ks++) {
#pragma unroll
            for (int n2 = 0; n2 < 8; n2++) {
                uint32_t b4[4];
                ldm4(b4, st + (uint32_t)((n2 * 16 + xrow) * QK_ST) + ks * 32 + xcol);
                mma16816(acc[n2 * 2 + 0], qf[ks], &b4[0]);
                mma16816(acc[n2 * 2 + 1], qf[ks], &b4[2]);
            }
        }

        uint32_t eh[32];
#pragma unroll
        for (int ni = 0; ni < 16; ni++) {
            const int col0 = kBase + ni * 8 + (lane & 3) * 2;
            float e00 = 0.f, e01 = 0.f, e10 = 0.f, e11 = 0.f;
            if (col0 < S_LEN) {
                e00 = __expf(acc[ni][0]); e01 = __expf(acc[ni][1]);
                e10 = __expf(acc[ni][2]); e11 = __expf(acc[ni][3]);
            }
            const __half2 hv0 = __floats2half2_rn(e00, e01);
            const __half2 hv1 = __floats2half2_rn(e10, e11);
            eh[ni * 2]     = *(const uint32_t*)&hv0;
            eh[ni * 2 + 1] = *(const uint32_t*)&hv1;
            if (col0 < S_LEN) {
                if (row0 < S_LEN) *reinterpret_cast<__half2*>(E + (hS + row0) * S_LEN + col0) = hv0;
                if (row1 < S_LEN) *reinterpret_cast<__half2*>(E + (hS + row1) * S_LEN + col0) = hv1;
                rsum0 += __low2float(hv0) + __high2float(hv0);
                rsum1 += __low2float(hv1) + __high2float(hv1);
            }
        }

#pragma unroll
        for (int ks = 0; ks < 8; ks++) {
#pragma unroll
            for (int n2 = 0; n2 < 4; n2++) {
                uint32_t b4[4];
                ldm4(b4, st + K_BYTES + (uint32_t)((n2 * 16 + xrow) * V_ST) + ks * 32 + xcol);
                mma16816(acc_o[n2 * 2 + 0], &eh[ks * 4], &b4[0]);
                mma16816(acc_o[n2 * 2 + 1], &eh[ks * 4], &b4[2]);
            }
        }

        __syncthreads();
        if (t + 2 < NT) issue_kv(t + 2);
        if (t + 1 < NT) {
            if (t + 2 < NT) cpwait<1>(); else cpwait<0>();
            __syncthreads();
        }
    }

    // ---- finalize: rowsums -> AO write ----
    rsum0 += __shfl_xor_sync(0xFFFFFFFFu, rsum0, 1);
    rsum0 += __shfl_xor_sync(0xFFFFFFFFu, rsum0, 2);
    rsum1 += __shfl_xor_sync(0xFFFFFFFFu, rsum1, 1);
    rsum1 += __shfl_xor_sync(0xFFFFFFFFu, rsum1, 2);
    const float inv0 = 1.0f / rsum0;
    const float inv1 = 1.0f / rsum1;

    if (row0 < S_LEN) {
#pragma unroll
        for (int ni = 0; ni < 8; ni++) {
            const int d = ni * 8 + (lane & 3) * 2;
            *reinterpret_cast<__half2*>(AO + (long)row0 * E_DIM + h * 64 + d) =
                __floats2half2_rn(acc_o[ni][0] * inv0, acc_o[ni][1] * inv0);
        }
    }
    if (row1 < S_LEN) {
#pragma unroll
        for (int ni = 0; ni < 8; ni++) {
            const int d = ni * 8 + (lane & 3) * 2;
            *reinterpret_cast<__half2*>(AO + (long)row1 * E_DIM + h * 64 + d) =
                __floats2half2_rn(acc_o[ni][2] * inv1, acc_o[ni][3] * inv1);
        }
    }

    // ---- normalize epilogue: warp streams its 16 rows, inv via shfl ----
    // __syncthreads at loop end ordered this CTA's E global stores; E rows
    // [mBase + w*16, mBase + w*16 + 16) were written entirely by this warp.
#pragma unroll 1
    for (int rr = 0; rr < 16; rr++) {
        const int row = mBase + w * 16 + rr;
        if (row >= S_LEN) continue;
        // inv for local row rr: rr<8 -> inv0 of lane 4*rr; else inv1 of lane 4*(rr-8)
        const float invA = __shfl_sync(0xFFFFFFFFu, inv0, (rr & 7) * 4);
        const float invB = __shfl_sync(0xFFFFFFFFu, inv1, (rr & 7) * 4);
        const float inv = (rr < 8) ? invA : invB;
        const __half* e = E + (hS + row) * S_LEN;
        float* wp = W + (hS + row) * S_LEN;
        for (int i = lane * 8; i < S_LEN; i += 32 * 8) {
            uint4 h4 = *(const uint4*)(e + i);
            const uint32_t hh[4] = {h4.x, h4.y, h4.z, h4.w};
            float o[8];
#pragma unroll
            for (int j = 0; j < 4; j++) {
                __half2 hb = *(const __half2*)&hh[j];
                o[j * 2 + 0] = __low2float(hb) * inv;
                o[j * 2 + 1] = __high2float(hb) * inv;
            }
            *(float4*)(wp + i)     = make_float4(o[0], o[1], o[2], o[3]);
            *(float4*)(wp + i + 4) = make_float4(o[4], o[5], o[6], o[7]);
        }
    }
}

// ---------------------------------------------------------------------------
// Small kernels
// ---------------------------------------------------------------------------
__global__ void splitH_kernel(const float* __restrict__ src, __half* __restrict__ dst, long n) {
    long i = ((long)blockIdx.x * blockDim.x + threadIdx.x) * 4;
    if (i >= n) return;
    float4 v = *(const float4*)(src + i);
    *(__half2*)(dst + i)     = __floats2half2_rn(v.x, v.y);
    *(__half2*)(dst + i + 2) = __floats2half2_rn(v.z, v.w);
}

__global__ void splitW4_kernel(const float* __restrict__ w0, const float* __restrict__ w1,
                               const float* __restrict__ w2, const float* __restrict__ w3,
                               __half* __restrict__ dstB) {
    const long nw = (long)E_DIM * E_DIM;
    const int z = blockIdx.z;
    const float* src = (z == 0) ? w0 : (z == 1) ? w1 : (z == 2) ? w2 : w3;
    __half* dst = dstB + (long)z * nw;
    long i = ((long)blockIdx.x * blockDim.x + threadIdx.x) * 4;
    if (i >= nw) return;
    float4 v = *(const float4*)(src + i);
    *(__half2*)(dst + i)     = __floats2half2_rn(v.x, v.y);
    *(__half2*)(dst + i + 2) = __floats2half2_rn(v.z, v.w);
}

__global__ void rope_split_kernel(const float* __restrict__ Q, const float* __restrict__ K,
                                  const float* __restrict__ cosp, const float* __restrict__ sinp) {
    const long total = (long)H_NUM * S_LEN * 32;
    long idx = (long)blockIdx.x * blockDim.x + threadIdx.x;
    if (idx >= total) return;
    const int d = (int)(idx & 31);
    const long hs = idx >> 5;
    const int s = (int)(hs % S_LEN);
    const long base = hs << 6;

    const float c1 = cosp[s * 64 + d], s1 = sinp[s * 64 + d];
    const float c2 = cosp[s * 64 + d + 32], s2 = sinp[s * 64 + d + 32];

    float q1 = Q[base + d], q2 = Q[base + d + 32];
    float k1 = K[base + d], k2 = K[base + d + 32];

    g_Qh[base + d]      = __float2half_rn((q1 * c1 - q2 * s1) * 0.125f);
    g_Qh[base + d + 32] = __float2half_rn((q2 * c2 + q1 * s2) * 0.125f);
    g_Kh[base + d]      = __float2half_rn(k1 * c1 - k2 * s1);
    g_Kh[base + d + 32] = __float2half_rn(k2 * c2 + k1 * s2);
}

__global__ void vtrans_kernel(const float* __restrict__ V) {
    __shared__ float tile[64][65];
    const int h = blockIdx.z;
    const int s0 = blockIdx.x * 64;
    const int t = threadIdx.x;
    for (int i = t; i < 4096; i += 256) {
        int s = i >> 6, d = i & 63;
        tile[s][d] = V[((long)h * S_LEN + s0 + s) * 64 + d];
    }
    __syncthreads();
    for (int i = t; i < 4096; i += 256) {
        int d = i >> 6, s = i & 63;
        g_Vt[((long)h * 64 + d) * S_LEN + s0 + s] = __float2half_rn(tile[s][d]);
    }
}

// ---------------------------------------------------------------------------
// Launch
// ---------------------------------------------------------------------------
extern "C" void kernel_launch(void* const* d_in, const int* in_sizes, int n_in,
                              void* d_out, int out_size) {
    const float* hidden = (const float*)d_in[0];
    const float* cosp   = (const float*)d_in[1];
    const float* sinp   = (const float*)d_in[2];
    const float* w[4]   = {(const float*)d_in[3], (const float*)d_in[4],
                           (const float*)d_in[5], (const float*)d_in[6]};

    float* out    = (float*)d_out;
    float* attn_w = out + (long)S_LEN * E_DIM;

    float* qkv; cudaGetSymbolAddress((void**)&qkv, g_qkv);
    __half *Hh, *Wh, *Qh, *Kh, *Vt, *E, *AO;
    cudaGetSymbolAddress((void**)&Hh, g_Hh);
    cudaGetSymbolAddress((void**)&Wh, g_Wh);
    cudaGetSymbolAddress((void**)&Qh, g_Qh);    cudaGetSymbolAddress((void**)&Kh, g_Kh);
    cudaGetSymbolAddress((void**)&Vt, g_Vt);
    cudaGetSymbolAddress((void**)&E, g_E);      cudaGetSymbolAddress((void**)&AO, g_AO);

    const int SMEM_PROJ = 2 * (128 * 80 + 128 * 80);                 // 40960
    const int SMEM_FA   = 128 * 176 + 2 * (128 * 176 + 64 * 272);    // 102400
    cudaFuncSetAttribute((const void*)mma_gemm<0>, cudaFuncAttributeMaxDynamicSharedMemorySize, SMEM_PROJ);
    cudaFuncSetAttribute((const void*)mma_gemm<1>, cudaFuncAttributeMaxDynamicSharedMemorySize, SMEM_PROJ);
    cudaFuncSetAttribute((const void*)fused_attn,  cudaFuncAttributeMaxDynamicSharedMemorySize, SMEM_FA);

    // 1) fp16 conversions
    {
        long n = (long)S_LEN * E_DIM;
        splitH_kernel<<<(int)((n / 4 + 255) / 256), 256>>>(hidden, Hh, n);
        long nw = (long)E_DIM * E_DIM;
        dim3 gw((unsigned)((nw / 4 + 255) / 256), 1, 4);
        splitW4_kernel<<<gw, 256>>>(w[0], w[1], w[2], w[3], Wh);
    }

    // 2) QKV projections (1-pass fp16), batched over z={q,k,v}
    {
        dim3 g(E_DIM / 128, (S_LEN + 127) / 128, 3);
        mma_gemm<1><<<g, 256, SMEM_PROJ>>>(Hh, E_DIM,
                                           Wh, E_DIM, (long)E_DIM * E_DIM,
                                           qkv, 0, 0, 32, S_LEN);
    }

    // 3) RoPE -> fp16 Q (scaled), K; V transpose (fp16)
    {
        long total = (long)H_NUM * S_LEN * 32;
        const long HSD = (long)H_NUM * S_LEN * D_DIM;
        rope_split_kernel<<<(int)((total + 255) / 256), 256>>>(qkv, qkv + HSD, cosp, sinp);
        dim3 gv(S_LEN / 64, 1, H_NUM);
        vtrans_kernel<<<gv, 256>>>(qkv + 2 * HSD);
    }

    // 4) fused attention: E + normalized AO + fp32 attn_weights, one kernel
    {
        dim3 g((S_LEN + 127) / 128, H_NUM);
        fused_attn<<<g, 256, SMEM_FA>>>(Qh, Kh, Vt, E, AO, attn_w);
    }

    // 5) out = AO Wo^T (1-pass fp16)
    {
        dim3 g(E_DIM / 128, (S_LEN + 127) / 128, 1);
        long nw = (long)E_DIM * E_DIM;
        mma_gemm<0><<<g, 256, SMEM_PROJ>>>(AO, E_DIM,
                                           Wh + 3 * nw, E_DIM, 0,
                                           out, E_DIM, 0, 32, S_LEN);
    }
}

// round 16
// speedup vs baseline: 1.3863x; 1.3863x over previous
#include <cuda_runtime.h>
#include <cuda_fp16.h>
#include <math.h>
#include <stdint.h>

#define S_LEN 3136
#define E_DIM 1024
#define H_NUM 16
#define D_DIM 64

// ---------------------------------------------------------------------------
// Device scratch (allocation is forbidden)
// ---------------------------------------------------------------------------
__device__ float g_qkv[3][H_NUM * S_LEN * D_DIM];   // fp32 head-major q,k,v

__device__ __align__(16) __half g_Hh[S_LEN * E_DIM];            // hidden fp16
__device__ __align__(16) __half g_Wh[4][E_DIM * E_DIM];         // weights fp16
__device__ __align__(16) __half g_Qh[H_NUM * S_LEN * D_DIM];    // q fp16 (scaled 1/8)
__device__ __align__(16) __half g_Kh[H_NUM * S_LEN * D_DIM];    // k fp16
__device__ __align__(16) __half g_Vt[H_NUM * D_DIM * S_LEN];    // [h][d][s] fp16
__device__ __align__(16) __half g_E[(long)H_NUM * S_LEN * S_LEN]; // unnormalized exp
__device__ __align__(16) __half g_AO[S_LEN * E_DIM];            // normalized attn out
__device__ float g_isum[H_NUM * S_LEN];                         // 1 / rowsum

// ---------------------------------------------------------------------------
// PTX helpers
// ---------------------------------------------------------------------------
__device__ __forceinline__ uint32_t smem_u32(const void* p) {
    uint32_t a;
    asm("{ .reg .u64 t; cvta.to.shared.u64 t, %1; cvt.u32.u64 %0, t; }" : "=r"(a) : "l"(p));
    return a;
}
__device__ __forceinline__ void cp16(uint32_t dst, const void* src, int srcsize) {
    asm volatile("cp.async.cg.shared.global [%0], [%1], 16, %2;"
                 :: "r"(dst), "l"(src), "r"(srcsize));
}
__device__ __forceinline__ void cpcommit() { asm volatile("cp.async.commit_group;"); }
template <int N> __device__ __forceinline__ void cpwait() {
    asm volatile("cp.async.wait_group %0;" :: "n"(N));
}
__device__ __forceinline__ void ldm4(uint32_t* r, uint32_t a) {
    asm volatile("ldmatrix.sync.aligned.m8n8.x4.shared.b16 {%0,%1,%2,%3}, [%4];"
                 : "=r"(r[0]), "=r"(r[1]), "=r"(r[2]), "=r"(r[3]) : "r"(a));
}
__device__ __forceinline__ void mma16816(float* d, const uint32_t* a, const uint32_t* b) {
    asm volatile("mma.sync.aligned.m16n8k16.row.col.f32.f16.f16.f32 "
                 "{%0,%1,%2,%3}, {%4,%5,%6,%7}, {%8,%9}, {%0,%1,%2,%3};"
                 : "+f"(d[0]), "+f"(d[1]), "+f"(d[2]), "+f"(d[3])
                 : "r"(a[0]), "r"(a[1]), "r"(a[2]), "r"(a[3]), "r"(b[0]), "r"(b[1]));
}

// ---------------------------------------------------------------------------
// fp16 single/single TN GEMM for QKV-proj and out-proj (ldm4-paired B).
// EPI 0: fp32 C[z*cBatch + m*ldc + n]
// EPI 1: fp32 head-major qkv: C[(z*H + (n>>6))*S*64 + m*64 + (n&63)]
// ---------------------------------------------------------------------------
template <int EPI>
__global__ void __launch_bounds__(256, 1) mma_gemm(
    const __half* __restrict__ A, long aRow,
    const __half* __restrict__ B, long bRow, long bBatch,
    float* __restrict__ C, long ldc, long cBatch,
    int kChunks, int M_valid) {

    constexpr int AST = 80;
    constexpr int A_BYTES = 128 * AST;
    constexpr int B_BYTES = 128 * AST;
    constexpr int STAGE = A_BYTES + B_BYTES;

    extern __shared__ char smem[];
    const uint32_t sb = smem_u32(smem);

    const int tid = threadIdx.x;
    const int wid = tid >> 5, lane = tid & 31;
    const int warpM = (wid / 4) * 64;
    const int warpN = (wid % 4) * 32;

    const int mBase = blockIdx.y * 128;
    const int nBase = blockIdx.x * 128;
    const int z = blockIdx.z;
    B += bBatch * z;

    const int xrow = (lane & 7) + ((lane >> 4) << 3);
    const int xcol = ((lane >> 3) & 1) * 16;

    float acc[4][4][4];
#pragma unroll
    for (int i = 0; i < 4; i++)
#pragma unroll
        for (int j = 0; j < 4; j++)
#pragma unroll
            for (int q = 0; q < 4; q++) acc[i][j][q] = 0.0f;

    auto issue_loads = [&](int c) {
        const long k0 = (long)c * 32;
        const uint32_t st = sb + (c & 1) * STAGE;
        for (int i = tid; i < 512; i += 256) {
            const int r = i >> 2, u = i & 3;
            const int row = mBase + r;
            const int ok = (row < M_valid) ? 16 : 0;
            const long srow = (row < M_valid) ? row : (M_valid - 1);
            cp16(st + r * AST + u * 16, A + srow * aRow + k0 + u * 8, ok);
        }
        for (int i = tid; i < 512; i += 256) {
            const int r = i >> 2, u = i & 3;
            cp16(st + A_BYTES + r * AST + u * 16, B + (long)(nBase + r) * bRow + k0 + u * 8, 16);
        }
        cpcommit();
    };

    issue_loads(0);

    for (int c = 0; c < kChunks; c++) {
        if (c + 1 < kChunks) { issue_loads(c + 1); cpwait<1>(); }
        else                 { cpwait<0>(); }
        __syncthreads();

        const uint32_t st = sb + (c & 1) * STAGE;
        const uint32_t aB = st, bB = st + A_BYTES;

#pragma unroll
        for (int s = 0; s < 2; s++) {
            uint32_t af[4][4], bf[2][4];
            const int arow = warpM + (lane & 15);
            const uint32_t acol = s * 32 + (lane >> 4) * 16;
#pragma unroll
            for (int mi = 0; mi < 4; mi++)
                ldm4(af[mi], aB + (uint32_t)((arow + mi * 16) * AST) + acol);
#pragma unroll
            for (int n2 = 0; n2 < 2; n2++)
                ldm4(bf[n2], bB + (uint32_t)((warpN + n2 * 16 + xrow) * AST) + s * 32 + xcol);
#pragma unroll
            for (int mi = 0; mi < 4; mi++)
#pragma unroll
                for (int n2 = 0; n2 < 2; n2++) {
                    mma16816(acc[mi][n2 * 2 + 0], af[mi], &bf[n2][0]);
                    mma16816(acc[mi][n2 * 2 + 1], af[mi], &bf[n2][2]);
                }
        }
        __syncthreads();
    }

#pragma unroll
    for (int mi = 0; mi < 4; mi++) {
#pragma unroll
        for (int ni = 0; ni < 4; ni++) {
            const int rl0 = warpM + mi * 16 + (lane >> 2);
            const int col0 = nBase + warpN + ni * 8 + (lane & 3) * 2;
#pragma unroll
            for (int h = 0; h < 2; h++) {
                const int row = mBase + rl0 + h * 8;
                if (row >= M_valid) continue;
                const float v0 = acc[mi][ni][h * 2 + 0];
                const float v1 = acc[mi][ni][h * 2 + 1];
                if (EPI == 0) {
                    C[(long)z * cBatch + (long)row * ldc + col0] = v0;
                    C[(long)z * cBatch + (long)row * ldc + col0 + 1] = v1;
                } else {
                    const long o0 = ((long)z * H_NUM + (col0 >> 6)) * S_LEN * 64 + (long)row * 64 + (col0 & 63);
                    C[o0] = v0;
                    C[o0 + 1] = v1;
                }
            }
        }
    }
}

// ---------------------------------------------------------------------------
// Fused attention (R13-proven): per (m-tile 128, head) CTA, loop 25 K/V tiles.
// hOff selects the head group (blockIdx.y + hOff).
// ---------------------------------------------------------------------------
__global__ void __launch_bounds__(256, 1) fused_attn(
    const __half* __restrict__ Qh, const __half* __restrict__ Kh,
    const __half* __restrict__ V,
    __half* __restrict__ E, __half* __restrict__ AO, float* __restrict__ isum,
    int hOff) {

    constexpr int QK_ST = 176;
    constexpr int V_ST  = 272;
    constexpr int Q_BYTES = 128 * QK_ST;
    constexpr int K_BYTES = 128 * QK_ST;
    constexpr int V_BYTES = 64 * V_ST;
    constexpr int STAGE = K_BYTES + V_BYTES;
    constexpr int NT = 25;

    extern __shared__ char smem[];
    const uint32_t sb = smem_u32(smem);
    const uint32_t qb = sb;
    const uint32_t stb = sb + Q_BYTES;

    const int tid = threadIdx.x;
    const int w = tid >> 5, lane = tid & 31;
    const int h = blockIdx.y + hOff;
    const int mBase = blockIdx.x * 128;
    const long hS = (long)h * S_LEN;

    for (int i = tid; i < 1024; i += 256) {
        const int r = i >> 3, u = i & 7;
        const int row = mBase + r;
        const int ok = (row < S_LEN) ? 16 : 0;
        const long srow = (row < S_LEN) ? row : (S_LEN - 1);
        cp16(qb + r * QK_ST + u * 16, Qh + (hS + srow) * 64 + u * 8, ok);
    }
    auto issue_kv = [&](int t) {
        const int kBase = t * 128;
        const uint32_t st = stb + (t & 1) * STAGE;
        for (int i = tid; i < 1024; i += 256) {
            const int r = i >> 3, u = i & 7;
            const int row = kBase + r;
            const int ok = (row < S_LEN) ? 16 : 0;
            const long srow = (row < S_LEN) ? row : (S_LEN - 1);
            cp16(st + r * QK_ST + u * 16, Kh + (hS + srow) * 64 + u * 8, ok);
        }
        for (int i = tid; i < 1024; i += 256) {
            const int r = i >> 4, u = i & 15;
            const int col = kBase + u * 8;
            const int ok = (col < S_LEN) ? 16 : 0;
            const long scol = (col < S_LEN) ? col : (S_LEN - 8);
            const long off = ((long)h * 64 + r) * S_LEN + scol;
            cp16(st + K_BYTES + r * V_ST + u * 16, V + off, ok);
        }
        cpcommit();
    };
    issue_kv(0);
    issue_kv(1);
    cpwait<1>();
    __syncthreads();

    uint32_t qf[4][4];
    {
        const int arow = w * 16 + (lane & 15);
        const uint32_t acol = (uint32_t)((lane >> 4) * 16);
#pragma unroll
        for (int ks = 0; ks < 4; ks++)
            ldm4(qf[ks], qb + (uint32_t)(arow * QK_ST) + ks * 32 + acol);
    }

    float acc_o[8][4];
#pragma unroll
    for (int i = 0; i < 8; i++)
#pragma unroll
        for (int q = 0; q < 4; q++) acc_o[i][q] = 0.0f;
    float rsum0 = 0.0f, rsum1 = 0.0f;

    const int row0 = mBase + w * 16 + (lane >> 2);
    const int row1 = row0 + 8;
    const int xrow = (lane & 7) + ((lane >> 4) << 3);
    const int xcol = ((lane >> 3) & 1) * 16;

    for (int t = 0; t < NT; t++) {
        const uint32_t st = stb + (t & 1) * STAGE;
        const int kBase = t * 128;

        float acc[16][4];
#pragma unroll
        for (int i = 0; i < 16; i++)
#pragma unroll
            for (int q = 0; q < 4; q++) acc[i][q] = 0.0f;
#pragma unroll
        for (int ks = 0; ks < 4; ks++) {
#pragma unroll
            for (int n2 = 0; n2 < 8; n2++) {
                uint32_t b4[4];
                ldm4(b4, st + (uint32_t)((n2 * 16 + xrow) * QK_ST) + ks * 32 + xcol);
                mma16816(acc[n2 * 2 + 0], qf[ks], &b4[0]);
                mma16816(acc[n2 * 2 + 1], qf[ks], &b4[2]);
            }
        }

        uint32_t eh[32];
#pragma unroll
        for (int ni = 0; ni < 16; ni++) {
            const int col0 = kBase + ni * 8 + (lane & 3) * 2;
            float e00 = 0.f, e01 = 0.f, e10 = 0.f, e11 = 0.f;
            if (col0 < S_LEN) {
                e00 = __expf(acc[ni][0]); e01 = __expf(acc[ni][1]);
                e10 = __expf(acc[ni][2]); e11 = __expf(acc[ni][3]);
            }
            const __half2 hv0 = __floats2half2_rn(e00, e01);
            const __half2 hv1 = __floats2half2_rn(e10, e11);
            eh[ni * 2]     = *(const uint32_t*)&hv0;
            eh[ni * 2 + 1] = *(const uint32_t*)&hv1;
            if (col0 < S_LEN) {
                if (row0 < S_LEN) *reinterpret_cast<__half2*>(E + (hS + row0) * S_LEN + col0) = hv0;
                if (row1 < S_LEN) *reinterpret_cast<__half2*>(E + (hS + row1) * S_LEN + col0) = hv1;
                rsum0 += __low2float(hv0) + __high2float(hv0);
                rsum1 += __low2float(hv1) + __high2float(hv1);
            }
        }

#pragma unroll
        for (int ks = 0; ks < 8; ks++) {
#pragma unroll
            for (int n2 = 0; n2 < 4; n2++) {
                uint32_t b4[4];
                ldm4(b4, st + K_BYTES + (uint32_t)((n2 * 16 + xrow) * V_ST) + ks * 32 + xcol);
                mma16816(acc_o[n2 * 2 + 0], &eh[ks * 4], &b4[0]);
                mma16816(acc_o[n2 * 2 + 1], &eh[ks * 4], &b4[2]);
            }
        }

        __syncthreads();
        if (t + 2 < NT) issue_kv(t + 2);
        if (t + 1 < NT) {
            if (t + 2 < NT) cpwait<1>(); else cpwait<0>();
            __syncthreads();
        }
    }

    // ---- finalize ----
    rsum0 += __shfl_xor_sync(0xFFFFFFFFu, rsum0, 1);
    rsum0 += __shfl_xor_sync(0xFFFFFFFFu, rsum0, 2);
    rsum1 += __shfl_xor_sync(0xFFFFFFFFu, rsum1, 1);
    rsum1 += __shfl_xor_sync(0xFFFFFFFFu, rsum1, 2);
    const float inv0 = 1.0f / rsum0;
    const float inv1 = 1.0f / rsum1;

    if (row0 < S_LEN) {
#pragma unroll
        for (int ni = 0; ni < 8; ni++) {
            const int d = ni * 8 + (lane & 3) * 2;
            *reinterpret_cast<__half2*>(AO + (long)row0 * E_DIM + h * 64 + d) =
                __floats2half2_rn(acc_o[ni][0] * inv0, acc_o[ni][1] * inv0);
        }
        if ((lane & 3) == 0) isum[hS + row0] = inv0;
    }
    if (row1 < S_LEN) {
#pragma unroll
        for (int ni = 0; ni < 8; ni++) {
            const int d = ni * 8 + (lane & 3) * 2;
            *reinterpret_cast<__half2*>(AO + (long)row1 * E_DIM + h * 64 + d) =
                __floats2half2_rn(acc_o[ni][2] * inv1, acc_o[ni][3] * inv1);
        }
        if ((lane & 3) == 0) isum[hS + row1] = inv1;
    }
}

// ---------------------------------------------------------------------------
// Small kernels
// ---------------------------------------------------------------------------
__global__ void splitH_kernel(const float* __restrict__ src, __half* __restrict__ dst, long n) {
    long i = ((long)blockIdx.x * blockDim.x + threadIdx.x) * 4;
    if (i >= n) return;
    float4 v = *(const float4*)(src + i);
    *(__half2*)(dst + i)     = __floats2half2_rn(v.x, v.y);
    *(__half2*)(dst + i + 2) = __floats2half2_rn(v.z, v.w);
}

__global__ void splitW4_kernel(const float* __restrict__ w0, const float* __restrict__ w1,
                               const float* __restrict__ w2, const float* __restrict__ w3,
                               __half* __restrict__ dstB) {
    const long nw = (long)E_DIM * E_DIM;
    const int z = blockIdx.z;
    const float* src = (z == 0) ? w0 : (z == 1) ? w1 : (z == 2) ? w2 : w3;
    __half* dst = dstB + (long)z * nw;
    long i = ((long)blockIdx.x * blockDim.x + threadIdx.x) * 4;
    if (i >= nw) return;
    float4 v = *(const float4*)(src + i);
    *(__half2*)(dst + i)     = __floats2half2_rn(v.x, v.y);
    *(__half2*)(dst + i + 2) = __floats2half2_rn(v.z, v.w);
}

__global__ void rope_split_kernel(const float* __restrict__ Q, const float* __restrict__ K,
                                  const float* __restrict__ cosp, const float* __restrict__ sinp) {
    const long total = (long)H_NUM * S_LEN * 32;
    long idx = (long)blockIdx.x * blockDim.x + threadIdx.x;
    if (idx >= total) return;
    const int d = (int)(idx & 31);
    const long hs = idx >> 5;
    const int s = (int)(hs % S_LEN);
    const long base = hs << 6;

    const float c1 = cosp[s * 64 + d], s1 = sinp[s * 64 + d];
    const float c2 = cosp[s * 64 + d + 32], s2 = sinp[s * 64 + d + 32];

    float q1 = Q[base + d], q2 = Q[base + d + 32];
    float k1 = K[base + d], k2 = K[base + d + 32];

    g_Qh[base + d]      = __float2half_rn((q1 * c1 - q2 * s1) * 0.125f);
    g_Qh[base + d + 32] = __float2half_rn((q2 * c2 + q1 * s2) * 0.125f);
    g_Kh[base + d]      = __float2half_rn(k1 * c1 - k2 * s1);
    g_Kh[base + d + 32] = __float2half_rn(k2 * c2 + k1 * s2);
}

__global__ void vtrans_kernel(const float* __restrict__ V) {
    __shared__ float tile[64][65];
    const int h = blockIdx.z;
    const int s0 = blockIdx.x * 64;
    const int t = threadIdx.x;
    for (int i = t; i < 4096; i += 256) {
        int s = i >> 6, d = i & 63;
        tile[s][d] = V[((long)h * S_LEN + s0 + s) * 64 + d];
    }
    __syncthreads();
    for (int i = t; i < 4096; i += 256) {
        int d = i >> 6, s = i & 63;
        g_Vt[((long)h * 64 + d) * S_LEN + s0 + s] = __float2half_rn(tile[s][d]);
    }
}

// one block per attention row (rowOff selects head group): attn_w = E * isum
__global__ void normalize_kernel(float* __restrict__ W, long rowOff) {
    const long row = blockIdx.x + rowOff;
    const float inv = g_isum[row];
    const __half* e = g_E + row * (long)S_LEN;
    float* w = W + row * (long)S_LEN;
    for (int i = threadIdx.x * 8; i < S_LEN; i += 256 * 8) {
        uint4 h4 = *(const uint4*)(e + i);
        const uint32_t hh[4] = {h4.x, h4.y, h4.z, h4.w};
        float o[8];
#pragma unroll
        for (int j = 0; j < 4; j++) {
            __half2 hb = *(const __half2*)&hh[j];
            o[j * 2 + 0] = __low2float(hb) * inv;
            o[j * 2 + 1] = __high2float(hb) * inv;
        }
        *(float4*)(w + i)     = make_float4(o[0], o[1], o[2], o[3]);
        *(float4*)(w + i + 4) = make_float4(o[4], o[5], o[6], o[7]);
    }
}

// ---------------------------------------------------------------------------
// Launch
// ---------------------------------------------------------------------------
extern "C" void kernel_launch(void* const* d_in, const int* in_sizes, int n_in,
                              void* d_out, int out_size) {
    const float* hidden = (const float*)d_in[0];
    const float* cosp   = (const float*)d_in[1];
    const float* sinp   = (const float*)d_in[2];
    const float* w[4]   = {(const float*)d_in[3], (const float*)d_in[4],
                           (const float*)d_in[5], (const float*)d_in[6]};

    float* out    = (float*)d_out;
    float* attn_w = out + (long)S_LEN * E_DIM;

    float* qkv; cudaGetSymbolAddress((void**)&qkv, g_qkv);
    __half *Hh, *Wh, *Qh, *Kh, *Vt, *E, *AO;
    float *isum;
    cudaGetSymbolAddress((void**)&Hh, g_Hh);
    cudaGetSymbolAddress((void**)&Wh, g_Wh);
    cudaGetSymbolAddress((void**)&Qh, g_Qh);    cudaGetSymbolAddress((void**)&Kh, g_Kh);
    cudaGetSymbolAddress((void**)&Vt, g_Vt);
    cudaGetSymbolAddress((void**)&E, g_E);      cudaGetSymbolAddress((void**)&AO, g_AO);
    cudaGetSymbolAddress((void**)&isum, g_isum);

    static cudaStream_t s1 = nullptr;
    static cudaEvent_t evA = nullptr, evB = nullptr, evJoin = nullptr;
    if (!s1) {
        cudaStreamCreateWithFlags(&s1, cudaStreamNonBlocking);
        cudaEventCreateWithFlags(&evA, cudaEventDisableTiming);
        cudaEventCreateWithFlags(&evB, cudaEventDisableTiming);
        cudaEventCreateWithFlags(&evJoin, cudaEventDisableTiming);
    }

    const int SMEM_PROJ = 2 * (128 * 80 + 128 * 80);                 // 40960
    const int SMEM_FA   = 128 * 176 + 2 * (128 * 176 + 64 * 272);    // 102400
    cudaFuncSetAttribute((const void*)mma_gemm<0>, cudaFuncAttributeMaxDynamicSharedMemorySize, SMEM_PROJ);
    cudaFuncSetAttribute((const void*)mma_gemm<1>, cudaFuncAttributeMaxDynamicSharedMemorySize, SMEM_PROJ);
    cudaFuncSetAttribute((const void*)fused_attn,  cudaFuncAttributeMaxDynamicSharedMemorySize, SMEM_FA);

    // 1) fp16 conversions
    {
        long n = (long)S_LEN * E_DIM;
        splitH_kernel<<<(int)((n / 4 + 255) / 256), 256>>>(hidden, Hh, n);
        long nw = (long)E_DIM * E_DIM;
        dim3 gw((unsigned)((nw / 4 + 255) / 256), 1, 4);
        splitW4_kernel<<<gw, 256>>>(w[0], w[1], w[2], w[3], Wh);
    }

    // 2) QKV projections (1-pass fp16), batched over z={q,k,v}
    {
        dim3 g(E_DIM / 128, (S_LEN + 127) / 128, 3);
        mma_gemm<1><<<g, 256, SMEM_PROJ>>>(Hh, E_DIM,
                                           Wh, E_DIM, (long)E_DIM * E_DIM,
                                           qkv, 0, 0, 32, S_LEN);
    }

    // 3) RoPE -> fp16 Q (scaled), K; V transpose (fp16)
    {
        long total = (long)H_NUM * S_LEN * 32;
        const long HSD = (long)H_NUM * S_LEN * D_DIM;
        rope_split_kernel<<<(int)((total + 255) / 256), 256>>>(qkv, qkv + HSD, cosp, sinp);
        dim3 gv(S_LEN / 64, 1, H_NUM);
        vtrans_kernel<<<gv, 256>>>(qkv + 2 * HSD);
    }

    // 4) fused attention, split into two head groups for pipelined normalize
    {
        dim3 g((S_LEN + 127) / 128, H_NUM / 2);
        fused_attn<<<g, 256, SMEM_FA>>>(Qh, Kh, Vt, E, AO, isum, 0);
        cudaEventRecord(evA, 0);
        fused_attn<<<g, 256, SMEM_FA>>>(Qh, Kh, Vt, E, AO, isum, H_NUM / 2);
        cudaEventRecord(evB, 0);
    }

    // 5) pipelined normalize on side stream:
    //    heads 0-7 overlap fused_attn(8-15); heads 8-15 overlap out-proj
    {
        const long half = (long)(H_NUM / 2) * S_LEN;
        cudaStreamWaitEvent(s1, evA, 0);
        normalize_kernel<<<(unsigned)half, 256, 0, s1>>>(attn_w, 0);
        cudaStreamWaitEvent(s1, evB, 0);
        normalize_kernel<<<(unsigned)half, 256, 0, s1>>>(attn_w, half);
        cudaEventRecord(evJoin, s1);
    }

    // 6) out = AO Wo^T (1-pass fp16)  [main stream, after fused_attn both halves]
    {
        dim3 g(E_DIM / 128, (S_LEN + 127) / 128, 1);
        long nw = (long)E_DIM * E_DIM;
        mma_gemm<0><<<g, 256, SMEM_PROJ>>>(AO, E_DIM,
                                           Wh + 3 * nw, E_DIM, 0,
                                           out, E_DIM, 0, 32, S_LEN);
    }

    // 7) JOIN
    cudaStreamWaitEvent(0, evJoin, 0);
}